// round 1
// baseline (speedup 1.0000x reference)
#include <cuda_runtime.h>
#include <math.h>

#define Bn  2
#define Sn  2048
#define Dn  2048
#define Hn  16
#define DKn 128
#define DVn 128
#define Ln  64

// ---------------- scratch (device globals; no allocation allowed) ----------------
__device__ float g_wqk[Dn * Hn * Ln];        // [2048][1024]  Wq absorbed with Wkr^T
__device__ float g_bqk[Hn * Ln];             // [1024]
__device__ float g_wvo[Hn * Ln * Dn];        // [1024][2048]  Wvr absorbed with Wout
__device__ float g_q [Bn * Hn * Sn * Ln];    // [B,H,S,L]
__device__ float g_lk[Bn * Hn * Sn * Ln];    // [B,H,S,L]
__device__ float g_lv[Bn * Hn * Sn * Ln];    // [B,H,S,L]
__device__ float g_olat[Bn * Sn * Hn * Ln];  // [4096][1024] (b,s,h,l)

// ---------------- weight precompute: Wqk[d, h*64+l] = sum_dk Wq[d,h*128+dk]*Wkr[l,dk]
__global__ void wqk_kernel(const float* __restrict__ Wq, const float* __restrict__ Wkr,
                           float* __restrict__ out)
{
    __shared__ float wkT[DKn][Ln];   // wkT[dk][l] = Wkr[l][dk]
    int t = threadIdx.x;             // 128 threads
    for (int i = t; i < Ln * DKn; i += 128) {
        int l = i >> 7, dk = i & 127;
        wkT[dk][l] = Wkr[i];
    }
    __syncthreads();
    int h = blockIdx.y;
    int d = blockIdx.x * 128 + t;
    const float* wq = Wq + (size_t)d * Dn + h * DKn;
    float s[Ln];
#pragma unroll
    for (int l = 0; l < Ln; l++) s[l] = 0.f;
    for (int dk = 0; dk < DKn; dk++) {
        float a = wq[dk];
        const float4* w4 = (const float4*)&wkT[dk][0];
#pragma unroll
        for (int l4 = 0; l4 < Ln / 4; l4++) {
            float4 w = w4[l4];
            s[l4*4+0] = fmaf(a, w.x, s[l4*4+0]);
            s[l4*4+1] = fmaf(a, w.y, s[l4*4+1]);
            s[l4*4+2] = fmaf(a, w.z, s[l4*4+2]);
            s[l4*4+3] = fmaf(a, w.w, s[l4*4+3]);
        }
    }
    float* o = out + (size_t)d * (Hn * Ln) + h * Ln;
#pragma unroll
    for (int l4 = 0; l4 < Ln / 4; l4++)
        *(float4*)&o[l4*4] = make_float4(s[l4*4], s[l4*4+1], s[l4*4+2], s[l4*4+3]);
}

// bqk[h*64+l] = sum_dk bq[h*128+dk] * Wkr[l,dk]
__global__ void bqk_kernel(const float* __restrict__ bq, const float* __restrict__ Wkr,
                           float* __restrict__ out)
{
    int hl = blockIdx.x * 256 + threadIdx.x;
    if (hl >= Hn * Ln) return;
    int h = hl >> 6, l = hl & 63;
    float s = 0.f;
#pragma unroll 8
    for (int dk = 0; dk < DKn; dk++)
        s = fmaf(bq[h * DKn + dk], Wkr[l * DKn + dk], s);
    out[hl] = s;
}

// Wvo[h*64+l, d] = sum_dv Wvr[l,dv] * Wout[h*128+dv, d]
__global__ void wvo_kernel(const float* __restrict__ Wvr, const float* __restrict__ Wout,
                           float* __restrict__ out)
{
    __shared__ float wvT[DVn][Ln];   // wvT[dv][l] = Wvr[l][dv]
    int t = threadIdx.x;             // 128 threads
    for (int i = t; i < Ln * DVn; i += 128) {
        int l = i >> 7, dv = i & 127;
        wvT[dv][l] = Wvr[i];
    }
    __syncthreads();
    int h = blockIdx.y;
    int d = blockIdx.x * 128 + t;
    float s[Ln];
#pragma unroll
    for (int l = 0; l < Ln; l++) s[l] = 0.f;
    for (int dv = 0; dv < DVn; dv++) {
        float a = Wout[(size_t)(h * DVn + dv) * Dn + d];
        const float4* w4 = (const float4*)&wvT[dv][0];
#pragma unroll
        for (int l4 = 0; l4 < Ln / 4; l4++) {
            float4 w = w4[l4];
            s[l4*4+0] = fmaf(a, w.x, s[l4*4+0]);
            s[l4*4+1] = fmaf(a, w.y, s[l4*4+1]);
            s[l4*4+2] = fmaf(a, w.z, s[l4*4+2]);
            s[l4*4+3] = fmaf(a, w.w, s[l4*4+3]);
        }
    }
    for (int l = 0; l < Ln; l++)
        out[(size_t)(h * Ln + l) * Dn + d] = s[l];
}

// ---------------- main SGEMM: C = A[M,K] @ B[K,N] + bias, optional remap to [B,H,S,L]
__global__ void __launch_bounds__(256, 2) sgemm128(
    const float* __restrict__ A, const float* __restrict__ B,
    const float* __restrict__ bias, float* __restrict__ C,
    int M, int N, int K, int remap)
{
    __shared__ float As[8][128];
    __shared__ float Bs[8][128];
    const int tid = threadIdx.x;
    const int bx = blockIdx.x, by = blockIdx.y;
    const int tx = tid & 15, ty = tid >> 4;

    float acc[8][8];
#pragma unroll
    for (int i = 0; i < 8; i++)
#pragma unroll
        for (int j = 0; j < 8; j++) acc[i][j] = 0.f;

    const int arow = tid >> 1, acol = (tid & 1) << 2;
    const int brow = tid >> 5, bcol = (tid & 31) << 2;
    const float* Ap = A + (size_t)(by * 128 + arow) * K + acol;
    const float* Bp = B + (size_t)brow * N + bx * 128 + bcol;

    for (int k0 = 0; k0 < K; k0 += 8) {
        float4 av = *(const float4*)(Ap + k0);
        float4 bv = *(const float4*)(Bp + (size_t)k0 * N);
        As[acol + 0][arow] = av.x;
        As[acol + 1][arow] = av.y;
        As[acol + 2][arow] = av.z;
        As[acol + 3][arow] = av.w;
        *(float4*)&Bs[brow][bcol] = bv;
        __syncthreads();
#pragma unroll
        for (int kk = 0; kk < 8; kk++) {
            float ra[8], rb[8];
            *(float4*)(ra + 0) = *(const float4*)&As[kk][ty * 8 + 0];
            *(float4*)(ra + 4) = *(const float4*)&As[kk][ty * 8 + 4];
            *(float4*)(rb + 0) = *(const float4*)&Bs[kk][tx * 8 + 0];
            *(float4*)(rb + 4) = *(const float4*)&Bs[kk][tx * 8 + 4];
#pragma unroll
            for (int i = 0; i < 8; i++)
#pragma unroll
                for (int j = 0; j < 8; j++)
                    acc[i][j] = fmaf(ra[i], rb[j], acc[i][j]);
        }
        __syncthreads();
    }

    const int rowbase = by * 128 + ty * 8;
    const int colbase = bx * 128 + tx * 8;
#pragma unroll
    for (int i = 0; i < 8; i++) {
        int row = rowbase + i;
#pragma unroll
        for (int j = 0; j < 8; j++) {
            int col = colbase + j;
            float v = acc[i][j] + bias[col];
            if (remap) {
                // row = b*Sn+s ; col = h*Ln+l  ->  [b,h,s,l]
                int b = row >> 11, s = row & 2047;
                int h = col >> 6,  l = col & 63;
                C[(((size_t)(b * Hn + h) * Sn + s) << 6) + l] = v;
            } else {
                C[(size_t)row * N + col] = v;
            }
        }
    }
}

// ---------------- flash attention in latent space (d=64, causal) ----------------
__global__ void __launch_bounds__(256) flash_kernel(
    const float* __restrict__ Q, const float* __restrict__ Kl,
    const float* __restrict__ Vl, float* __restrict__ O)
{
    extern __shared__ float sm[];
    float* Qs  = sm;                 // [64][64]
    float* KPs = sm + 64 * 64;       // [64][65]  (K tile, reused as P tile)
    float* Vs  = sm + 64 * 64 + 64 * 65;  // [64][64]

    const int tid = threadIdx.x;
    const int tx = tid & 15, ty = tid >> 4;
    const int bh = blockIdx.y;            // b*16+h
    const int qt = blockIdx.x;
    const int q0 = qt * 64;
    const float scale = 0.08838834764831845f;  // 1/sqrt(128)

    const float* Qb = Q  + ((size_t)bh * Sn + q0) * Ln;
    const float* Kb = Kl + (size_t)bh * Sn * Ln;
    const float* Vb = Vl + (size_t)bh * Sn * Ln;

    for (int i = tid; i < 64 * 16; i += 256) {
        int r = i >> 4, c = (i & 15) << 2;
        float4 v = *(const float4*)(Qb + r * 64 + c);
        Qs[r * 64 + c + 0] = v.x * scale;
        Qs[r * 64 + c + 1] = v.y * scale;
        Qs[r * 64 + c + 2] = v.z * scale;
        Qs[r * 64 + c + 3] = v.w * scale;
    }

    float m[4], l[4], acc[4][4];
#pragma unroll
    for (int i = 0; i < 4; i++) {
        m[i] = -1e30f; l[i] = 0.f;
#pragma unroll
        for (int j = 0; j < 4; j++) acc[i][j] = 0.f;
    }

    for (int kt = 0; kt <= qt; kt++) {
        __syncthreads();   // protect previous iteration's P reads / V reads
        for (int i = tid; i < 64 * 16; i += 256) {
            int r = i >> 4, c = (i & 15) << 2;
            float4 kv = *(const float4*)(Kb + (size_t)(kt * 64 + r) * 64 + c);
            KPs[r * 65 + c + 0] = kv.x;
            KPs[r * 65 + c + 1] = kv.y;
            KPs[r * 65 + c + 2] = kv.z;
            KPs[r * 65 + c + 3] = kv.w;
            float4 vv = *(const float4*)(Vb + (size_t)(kt * 64 + r) * 64 + c);
            *(float4*)&Vs[r * 64 + c] = vv;
        }
        __syncthreads();

        // scores S = Q K^T  (4x4 microtile)
        float s[4][4];
#pragma unroll
        for (int i = 0; i < 4; i++)
#pragma unroll
            for (int j = 0; j < 4; j++) s[i][j] = 0.f;
#pragma unroll 8
        for (int d = 0; d < 64; d++) {
            float a0 = Qs[(ty * 4 + 0) * 64 + d];
            float a1 = Qs[(ty * 4 + 1) * 64 + d];
            float a2 = Qs[(ty * 4 + 2) * 64 + d];
            float a3 = Qs[(ty * 4 + 3) * 64 + d];
            float b0 = KPs[(tx * 4 + 0) * 65 + d];
            float b1 = KPs[(tx * 4 + 1) * 65 + d];
            float b2 = KPs[(tx * 4 + 2) * 65 + d];
            float b3 = KPs[(tx * 4 + 3) * 65 + d];
            s[0][0] = fmaf(a0, b0, s[0][0]); s[0][1] = fmaf(a0, b1, s[0][1]);
            s[0][2] = fmaf(a0, b2, s[0][2]); s[0][3] = fmaf(a0, b3, s[0][3]);
            s[1][0] = fmaf(a1, b0, s[1][0]); s[1][1] = fmaf(a1, b1, s[1][1]);
            s[1][2] = fmaf(a1, b2, s[1][2]); s[1][3] = fmaf(a1, b3, s[1][3]);
            s[2][0] = fmaf(a2, b0, s[2][0]); s[2][1] = fmaf(a2, b1, s[2][1]);
            s[2][2] = fmaf(a2, b2, s[2][2]); s[2][3] = fmaf(a2, b3, s[2][3]);
            s[3][0] = fmaf(a3, b0, s[3][0]); s[3][1] = fmaf(a3, b1, s[3][1]);
            s[3][2] = fmaf(a3, b2, s[3][2]); s[3][3] = fmaf(a3, b3, s[3][3]);
        }

        if (kt == qt) {
#pragma unroll
            for (int i = 0; i < 4; i++)
#pragma unroll
                for (int j = 0; j < 4; j++)
                    if (tx * 4 + j > ty * 4 + i) s[i][j] = -1e30f;
        }

        // online softmax (row reduction over the 16 tx lanes = half-warp)
        float p[4][4];
#pragma unroll
        for (int i = 0; i < 4; i++) {
            float rm = fmaxf(fmaxf(s[i][0], s[i][1]), fmaxf(s[i][2], s[i][3]));
#pragma unroll
            for (int o = 8; o >= 1; o >>= 1)
                rm = fmaxf(rm, __shfl_xor_sync(0xffffffffu, rm, o, 16));
            float mn = fmaxf(m[i], rm);
            float fac = __expf(m[i] - mn);
            float rs = 0.f;
#pragma unroll
            for (int j = 0; j < 4; j++) {
                p[i][j] = __expf(s[i][j] - mn);
                rs += p[i][j];
            }
#pragma unroll
            for (int o = 8; o >= 1; o >>= 1)
                rs += __shfl_xor_sync(0xffffffffu, rs, o, 16);
            l[i] = l[i] * fac + rs;
            m[i] = mn;
#pragma unroll
            for (int j = 0; j < 4; j++) acc[i][j] *= fac;
        }

        __syncthreads();   // everyone done reading KPs as K
#pragma unroll
        for (int i = 0; i < 4; i++)
#pragma unroll
            for (int j = 0; j < 4; j++)
                KPs[(ty * 4 + i) * 65 + tx * 4 + j] = p[i][j];
        __syncthreads();

        // O += P @ V
#pragma unroll 4
        for (int c = 0; c < 64; c++) {
            float a0 = KPs[(ty * 4 + 0) * 65 + c];
            float a1 = KPs[(ty * 4 + 1) * 65 + c];
            float a2 = KPs[(ty * 4 + 2) * 65 + c];
            float a3 = KPs[(ty * 4 + 3) * 65 + c];
            float4 bv = *(const float4*)&Vs[c * 64 + tx * 4];
            acc[0][0] = fmaf(a0, bv.x, acc[0][0]); acc[0][1] = fmaf(a0, bv.y, acc[0][1]);
            acc[0][2] = fmaf(a0, bv.z, acc[0][2]); acc[0][3] = fmaf(a0, bv.w, acc[0][3]);
            acc[1][0] = fmaf(a1, bv.x, acc[1][0]); acc[1][1] = fmaf(a1, bv.y, acc[1][1]);
            acc[1][2] = fmaf(a1, bv.z, acc[1][2]); acc[1][3] = fmaf(a1, bv.w, acc[1][3]);
            acc[2][0] = fmaf(a2, bv.x, acc[2][0]); acc[2][1] = fmaf(a2, bv.y, acc[2][1]);
            acc[2][2] = fmaf(a2, bv.z, acc[2][2]); acc[2][3] = fmaf(a2, bv.w, acc[2][3]);
            acc[3][0] = fmaf(a3, bv.x, acc[3][0]); acc[3][1] = fmaf(a3, bv.y, acc[3][1]);
            acc[3][2] = fmaf(a3, bv.z, acc[3][2]); acc[3][3] = fmaf(a3, bv.w, acc[3][3]);
        }
    }

    const int b = bh >> 4, h = bh & 15;
#pragma unroll
    for (int i = 0; i < 4; i++) {
        float inv = 1.0f / l[i];
        int row = q0 + ty * 4 + i;
        float* o = O + ((size_t)(b * Sn + row)) * (Hn * Ln) + h * Ln + tx * 4;
#pragma unroll
        for (int j = 0; j < 4; j++) o[j] = acc[i][j] * inv;
    }
}

// ---------------- launch ----------------
extern "C" void kernel_launch(void* const* d_in, const int* in_sizes, int n_in,
                              void* d_out, int out_size)
{
    (void)in_sizes; (void)n_in; (void)out_size;
    const float* queries = (const float*)d_in[0];
    const float* keys    = (const float*)d_in[1];
    const float* values  = (const float*)d_in[2];
    const float* Wq      = (const float*)d_in[3];
    const float* bq      = (const float*)d_in[4];
    const float* Wlk     = (const float*)d_in[5];
    const float* blk     = (const float*)d_in[6];
    const float* Wlv     = (const float*)d_in[7];
    const float* blv     = (const float*)d_in[8];
    const float* Wkr     = (const float*)d_in[9];
    const float* Wvr     = (const float*)d_in[10];
    const float* Wout    = (const float*)d_in[11];
    const float* bout    = (const float*)d_in[12];
    float* out = (float*)d_out;

    float *wqk, *bqk, *wvo, *q, *lk, *lv, *olat;
    cudaGetSymbolAddress((void**)&wqk,  g_wqk);
    cudaGetSymbolAddress((void**)&bqk,  g_bqk);
    cudaGetSymbolAddress((void**)&wvo,  g_wvo);
    cudaGetSymbolAddress((void**)&q,    g_q);
    cudaGetSymbolAddress((void**)&lk,   g_lk);
    cudaGetSymbolAddress((void**)&lv,   g_lv);
    cudaGetSymbolAddress((void**)&olat, g_olat);

    const int flash_smem = (64 * 64 + 64 * 65 + 64 * 64) * 4;  // 49408 B
    cudaFuncSetAttribute(flash_kernel, cudaFuncAttributeMaxDynamicSharedMemorySize,
                         flash_smem);

    // absorbed weights
    wqk_kernel<<<dim3(16, 16), 128>>>(Wq, Wkr, wqk);
    bqk_kernel<<<4, 256>>>(bq, Wkr, bqk);
    wvo_kernel<<<dim3(16, 16), 128>>>(Wvr, Wout, wvo);

    // projections into latent space: [4096,2048]@[2048,1024] each
    sgemm128<<<dim3(8, 32), 256>>>(queries, wqk, bqk, q,  4096, 1024, 2048, 1);
    sgemm128<<<dim3(8, 32), 256>>>(keys,    Wlk, blk, lk, 4096, 1024, 2048, 1);
    sgemm128<<<dim3(8, 32), 256>>>(values,  Wlv, blv, lv, 4096, 1024, 2048, 1);

    // causal latent attention
    flash_kernel<<<dim3(Sn / 64, Bn * Hn), 256, flash_smem>>>(q, lk, lv, olat);

    // output projection: [4096,1024]@[1024,2048]
    sgemm128<<<dim3(16, 32), 256>>>(olat, wvo, bout, out, 4096, 2048, 1024, 0);
}

// round 2
// speedup vs baseline: 2.0781x; 2.0781x over previous
#include <cuda_runtime.h>
#include <math.h>
#include <stdint.h>

#define Bn  2
#define Sn  2048
#define Dn  2048
#define Hn  16
#define DKn 128
#define DVn 128
#define Ln  64

// ---------------- scratch (device globals; no allocation allowed) ----------------
__device__ float g_wqk[Dn * Hn * Ln];        // [2048][1024]  Wq absorbed with Wkr^T
__device__ float g_bqk[Hn * Ln];             // [1024]
__device__ float g_wvo[Hn * Ln * Dn];        // [1024][2048]  Wvr absorbed with Wout
__device__ float g_q [Bn * Hn * Sn * Ln];    // [B,H,S,L]
__device__ float g_lk[Bn * Hn * Sn * Ln];    // [B,H,S,L]
__device__ float g_lv[Bn * Hn * Sn * Ln];    // [B,H,S,L]
__device__ float g_olat[Bn * Sn * Hn * Ln];  // [4096][1024] (b,s,h,l)

// ---------------- weight precompute: Wqk[d, h*64+l] = sum_dk Wq[d,h*128+dk]*Wkr[l,dk]
__global__ void wqk_kernel(const float* __restrict__ Wq, const float* __restrict__ Wkr,
                           float* __restrict__ out)
{
    __shared__ float wkT[DKn][Ln];   // wkT[dk][l] = Wkr[l][dk]
    int t = threadIdx.x;             // 128 threads
    for (int i = t; i < Ln * DKn; i += 128) {
        int l = i >> 7, dk = i & 127;
        wkT[dk][l] = Wkr[i];
    }
    __syncthreads();
    int h = blockIdx.y;
    int d = blockIdx.x * 128 + t;
    const float* wq = Wq + (size_t)d * Dn + h * DKn;
    float s[Ln];
#pragma unroll
    for (int l = 0; l < Ln; l++) s[l] = 0.f;
    for (int dk = 0; dk < DKn; dk++) {
        float a = wq[dk];
        const float4* w4 = (const float4*)&wkT[dk][0];
#pragma unroll
        for (int l4 = 0; l4 < Ln / 4; l4++) {
            float4 w = w4[l4];
            s[l4*4+0] = fmaf(a, w.x, s[l4*4+0]);
            s[l4*4+1] = fmaf(a, w.y, s[l4*4+1]);
            s[l4*4+2] = fmaf(a, w.z, s[l4*4+2]);
            s[l4*4+3] = fmaf(a, w.w, s[l4*4+3]);
        }
    }
    float* o = out + (size_t)d * (Hn * Ln) + h * Ln;
#pragma unroll
    for (int l4 = 0; l4 < Ln / 4; l4++)
        *(float4*)&o[l4*4] = make_float4(s[l4*4], s[l4*4+1], s[l4*4+2], s[l4*4+3]);
}

// bqk[h*64+l] = sum_dk bq[h*128+dk] * Wkr[l,dk]
__global__ void bqk_kernel(const float* __restrict__ bq, const float* __restrict__ Wkr,
                           float* __restrict__ out)
{
    int hl = blockIdx.x * 256 + threadIdx.x;
    if (hl >= Hn * Ln) return;
    int h = hl >> 6, l = hl & 63;
    float s = 0.f;
#pragma unroll 8
    for (int dk = 0; dk < DKn; dk++)
        s = fmaf(bq[h * DKn + dk], Wkr[l * DKn + dk], s);
    out[hl] = s;
}

// Wvo[h*64+l, d] = sum_dv Wvr[l,dv] * Wout[h*128+dv, d]
__global__ void wvo_kernel(const float* __restrict__ Wvr, const float* __restrict__ Wout,
                           float* __restrict__ out)
{
    __shared__ float wvT[DVn][Ln];   // wvT[dv][l] = Wvr[l][dv]
    int t = threadIdx.x;             // 128 threads
    for (int i = t; i < Ln * DVn; i += 128) {
        int l = i >> 7, dv = i & 127;
        wvT[dv][l] = Wvr[i];
    }
    __syncthreads();
    int h = blockIdx.y;
    int d = blockIdx.x * 128 + t;
    float s[Ln];
#pragma unroll
    for (int l = 0; l < Ln; l++) s[l] = 0.f;
    for (int dv = 0; dv < DVn; dv++) {
        float a = Wout[(size_t)(h * DVn + dv) * Dn + d];
        const float4* w4 = (const float4*)&wvT[dv][0];
#pragma unroll
        for (int l4 = 0; l4 < Ln / 4; l4++) {
            float4 w = w4[l4];
            s[l4*4+0] = fmaf(a, w.x, s[l4*4+0]);
            s[l4*4+1] = fmaf(a, w.y, s[l4*4+1]);
            s[l4*4+2] = fmaf(a, w.z, s[l4*4+2]);
            s[l4*4+3] = fmaf(a, w.w, s[l4*4+3]);
        }
    }
    for (int l = 0; l < Ln; l++)
        out[(size_t)(h * Ln + l) * Dn + d] = s[l];
}

// ================= TF32 tensor-core GEMM =================
// C[M,N] = A[M,K] @ B[K,N] + bias, optional remap to [B,H,S,L]
// 128x128 block tile, BK=32, cp.async double buffer, mma.sync m16n8k8 tf32.
#define BM 128
#define BN 128
#define BK 32
#define ASTR 36    // stride mod 32 = 4 -> conflict-free A frag loads
#define BSTR 136   // stride mod 32 = 8 -> conflict-free B frag loads

__device__ __forceinline__ uint32_t f2tf32(float x) {
    uint32_t u;
    asm("cvt.rna.tf32.f32 %0, %1;" : "=r"(u) : "f"(x));
    return u;
}

__global__ void __launch_bounds__(256, 2) tf32gemm(
    const float* __restrict__ A, const float* __restrict__ B,
    const float* __restrict__ bias, float* __restrict__ C,
    int M, int N, int K, int remap)
{
    extern __shared__ float sm[];
    float (*As)[BM][ASTR] = (float (*)[BM][ASTR])sm;                  // [2][128][36]
    float (*Bs)[BK][BSTR] = (float (*)[BK][BSTR])(sm + 2 * BM * ASTR); // [2][32][136]

    const int tid  = threadIdx.x;
    const int lane = tid & 31, wid = tid >> 5;
    const int wm = wid & 3, wn = wid >> 2;        // 4x2 warp grid
    const int g  = lane >> 2, tg = lane & 3;

    // copy assignments (coalesced 128B per 8 lanes)
    const int ar = tid >> 3;            // A row (0..31), +32 per pass
    const int ac = (tid & 7) * 4;       // A k-offset (float4)
    const int bk = tid >> 3;            // B k-row (0..31)
    const int bc = (tid & 7) * 4;       // B n-offset, +32 per pass

    const float* Ab = A + (size_t)(blockIdx.y * BM) * K;
    const float* Bb = B + blockIdx.x * BN;

    float acc[2][8][4];
#pragma unroll
    for (int i = 0; i < 2; i++)
#pragma unroll
        for (int j = 0; j < 8; j++)
#pragma unroll
            for (int v = 0; v < 4; v++) acc[i][j][v] = 0.f;

    const int NKB = K / BK;

    // preload tile 0 into buf 0
    {
#pragma unroll
        for (int p = 0; p < 4; p++) {
            unsigned d = (unsigned)__cvta_generic_to_shared(&As[0][ar + 32 * p][ac]);
            const float* s = Ab + (size_t)(ar + 32 * p) * K + ac;
            asm volatile("cp.async.cg.shared.global [%0], [%1], 16;\n" :: "r"(d), "l"(s));
        }
#pragma unroll
        for (int j = 0; j < 4; j++) {
            unsigned d = (unsigned)__cvta_generic_to_shared(&Bs[0][bk][bc + 32 * j]);
            const float* s = Bb + (size_t)bk * N + bc + 32 * j;
            asm volatile("cp.async.cg.shared.global [%0], [%1], 16;\n" :: "r"(d), "l"(s));
        }
        asm volatile("cp.async.commit_group;\n");
    }

    int buf = 0;
    for (int kb = 0; kb < NKB; kb++) {
        if (kb + 1 < NKB) {
            const int k0 = (kb + 1) * BK;
#pragma unroll
            for (int p = 0; p < 4; p++) {
                unsigned d = (unsigned)__cvta_generic_to_shared(&As[buf ^ 1][ar + 32 * p][ac]);
                const float* s = Ab + (size_t)(ar + 32 * p) * K + k0 + ac;
                asm volatile("cp.async.cg.shared.global [%0], [%1], 16;\n" :: "r"(d), "l"(s));
            }
#pragma unroll
            for (int j = 0; j < 4; j++) {
                unsigned d = (unsigned)__cvta_generic_to_shared(&Bs[buf ^ 1][bk][bc + 32 * j]);
                const float* s = Bb + (size_t)(k0 + bk) * N + bc + 32 * j;
                asm volatile("cp.async.cg.shared.global [%0], [%1], 16;\n" :: "r"(d), "l"(s));
            }
        }
        asm volatile("cp.async.commit_group;\n");
        asm volatile("cp.async.wait_group 1;\n");
        __syncthreads();

#pragma unroll
        for (int kk = 0; kk < 4; kk++) {
            const int k8 = kk * 8;
            uint32_t af[2][4];
#pragma unroll
            for (int mi = 0; mi < 2; mi++) {
                const int r = wm * 32 + mi * 16 + g;
                af[mi][0] = f2tf32(As[buf][r    ][k8 + tg]);
                af[mi][1] = f2tf32(As[buf][r + 8][k8 + tg]);
                af[mi][2] = f2tf32(As[buf][r    ][k8 + tg + 4]);
                af[mi][3] = f2tf32(As[buf][r + 8][k8 + tg + 4]);
            }
#pragma unroll
            for (int nt = 0; nt < 8; nt++) {
                const int n = wn * 64 + nt * 8 + g;
                uint32_t b0 = f2tf32(Bs[buf][k8 + tg    ][n]);
                uint32_t b1 = f2tf32(Bs[buf][k8 + tg + 4][n]);
#pragma unroll
                for (int mi = 0; mi < 2; mi++) {
                    asm volatile(
                        "mma.sync.aligned.m16n8k8.row.col.f32.tf32.tf32.f32 "
                        "{%0,%1,%2,%3}, {%4,%5,%6,%7}, {%8,%9}, {%0,%1,%2,%3};\n"
                        : "+f"(acc[mi][nt][0]), "+f"(acc[mi][nt][1]),
                          "+f"(acc[mi][nt][2]), "+f"(acc[mi][nt][3])
                        : "r"(af[mi][0]), "r"(af[mi][1]), "r"(af[mi][2]), "r"(af[mi][3]),
                          "r"(b0), "r"(b1));
                }
            }
        }
        __syncthreads();
        buf ^= 1;
    }

    // epilogue: bias + (optional) remap to [B,H,S,L]
    const int rowb = blockIdx.y * BM + wm * 32 + g;
    const int colb = blockIdx.x * BN + wn * 64 + 2 * tg;
#pragma unroll
    for (int mi = 0; mi < 2; mi++) {
#pragma unroll
        for (int nt = 0; nt < 8; nt++) {
            const int col = colb + nt * 8;
            const float bv0 = bias[col], bv1 = bias[col + 1];
            const int r0 = rowb + mi * 16;
            const int r1 = r0 + 8;
            float2 v0 = make_float2(acc[mi][nt][0] + bv0, acc[mi][nt][1] + bv1);
            float2 v1 = make_float2(acc[mi][nt][2] + bv0, acc[mi][nt][3] + bv1);
            if (remap) {
                const int h = col >> 6, l = col & 63;
                {
                    const int b = r0 >> 11, s = r0 & 2047;
                    *(float2*)&C[(((size_t)(b * Hn + h) * Sn + s) << 6) + l] = v0;
                }
                {
                    const int b = r1 >> 11, s = r1 & 2047;
                    *(float2*)&C[(((size_t)(b * Hn + h) * Sn + s) << 6) + l] = v1;
                }
            } else {
                *(float2*)&C[(size_t)r0 * N + col] = v0;
                *(float2*)&C[(size_t)r1 * N + col] = v1;
            }
        }
    }
}

// ---------------- flash attention in latent space (d=64, causal) ----------------
__global__ void __launch_bounds__(256) flash_kernel(
    const float* __restrict__ Q, const float* __restrict__ Kl,
    const float* __restrict__ Vl, float* __restrict__ O)
{
    extern __shared__ float sm[];
    float* Qs  = sm;                 // [64][64]
    float* KPs = sm + 64 * 64;       // [64][65]  (K tile, reused as P tile)
    float* Vs  = sm + 64 * 64 + 64 * 65;  // [64][64]

    const int tid = threadIdx.x;
    const int tx = tid & 15, ty = tid >> 4;
    const int bh = blockIdx.y;            // b*16+h
    const int qt = blockIdx.x;
    const int q0 = qt * 64;
    const float scale = 0.08838834764831845f;  // 1/sqrt(128)

    const float* Qb = Q  + ((size_t)bh * Sn + q0) * Ln;
    const float* Kb = Kl + (size_t)bh * Sn * Ln;
    const float* Vb = Vl + (size_t)bh * Sn * Ln;

    for (int i = tid; i < 64 * 16; i += 256) {
        int r = i >> 4, c = (i & 15) << 2;
        float4 v = *(const float4*)(Qb + r * 64 + c);
        Qs[r * 64 + c + 0] = v.x * scale;
        Qs[r * 64 + c + 1] = v.y * scale;
        Qs[r * 64 + c + 2] = v.z * scale;
        Qs[r * 64 + c + 3] = v.w * scale;
    }

    float m[4], l[4], acc[4][4];
#pragma unroll
    for (int i = 0; i < 4; i++) {
        m[i] = -1e30f; l[i] = 0.f;
#pragma unroll
        for (int j = 0; j < 4; j++) acc[i][j] = 0.f;
    }

    for (int kt = 0; kt <= qt; kt++) {
        __syncthreads();   // protect previous iteration's P reads / V reads
        for (int i = tid; i < 64 * 16; i += 256) {
            int r = i >> 4, c = (i & 15) << 2;
            float4 kv = *(const float4*)(Kb + (size_t)(kt * 64 + r) * 64 + c);
            KPs[r * 65 + c + 0] = kv.x;
            KPs[r * 65 + c + 1] = kv.y;
            KPs[r * 65 + c + 2] = kv.z;
            KPs[r * 65 + c + 3] = kv.w;
            float4 vv = *(const float4*)(Vb + (size_t)(kt * 64 + r) * 64 + c);
            *(float4*)&Vs[r * 64 + c] = vv;
        }
        __syncthreads();

        // scores S = Q K^T  (4x4 microtile)
        float s[4][4];
#pragma unroll
        for (int i = 0; i < 4; i++)
#pragma unroll
            for (int j = 0; j < 4; j++) s[i][j] = 0.f;
#pragma unroll 8
        for (int d = 0; d < 64; d++) {
            float a0 = Qs[(ty * 4 + 0) * 64 + d];
            float a1 = Qs[(ty * 4 + 1) * 64 + d];
            float a2 = Qs[(ty * 4 + 2) * 64 + d];
            float a3 = Qs[(ty * 4 + 3) * 64 + d];
            float b0 = KPs[(tx * 4 + 0) * 65 + d];
            float b1 = KPs[(tx * 4 + 1) * 65 + d];
            float b2 = KPs[(tx * 4 + 2) * 65 + d];
            float b3 = KPs[(tx * 4 + 3) * 65 + d];
            s[0][0] = fmaf(a0, b0, s[0][0]); s[0][1] = fmaf(a0, b1, s[0][1]);
            s[0][2] = fmaf(a0, b2, s[0][2]); s[0][3] = fmaf(a0, b3, s[0][3]);
            s[1][0] = fmaf(a1, b0, s[1][0]); s[1][1] = fmaf(a1, b1, s[1][1]);
            s[1][2] = fmaf(a1, b2, s[1][2]); s[1][3] = fmaf(a1, b3, s[1][3]);
            s[2][0] = fmaf(a2, b0, s[2][0]); s[2][1] = fmaf(a2, b1, s[2][1]);
            s[2][2] = fmaf(a2, b2, s[2][2]); s[2][3] = fmaf(a2, b3, s[2][3]);
            s[3][0] = fmaf(a3, b0, s[3][0]); s[3][1] = fmaf(a3, b1, s[3][1]);
            s[3][2] = fmaf(a3, b2, s[3][2]); s[3][3] = fmaf(a3, b3, s[3][3]);
        }

        if (kt == qt) {
#pragma unroll
            for (int i = 0; i < 4; i++)
#pragma unroll
                for (int j = 0; j < 4; j++)
                    if (tx * 4 + j > ty * 4 + i) s[i][j] = -1e30f;
        }

        // online softmax (row reduction over the 16 tx lanes = half-warp)
        float p[4][4];
#pragma unroll
        for (int i = 0; i < 4; i++) {
            float rm = fmaxf(fmaxf(s[i][0], s[i][1]), fmaxf(s[i][2], s[i][3]));
#pragma unroll
            for (int o = 8; o >= 1; o >>= 1)
                rm = fmaxf(rm, __shfl_xor_sync(0xffffffffu, rm, o, 16));
            float mn = fmaxf(m[i], rm);
            float fac = __expf(m[i] - mn);
            float rs = 0.f;
#pragma unroll
            for (int j = 0; j < 4; j++) {
                p[i][j] = __expf(s[i][j] - mn);
                rs += p[i][j];
            }
#pragma unroll
            for (int o = 8; o >= 1; o >>= 1)
                rs += __shfl_xor_sync(0xffffffffu, rs, o, 16);
            l[i] = l[i] * fac + rs;
            m[i] = mn;
#pragma unroll
            for (int j = 0; j < 4; j++) acc[i][j] *= fac;
        }

        __syncthreads();   // everyone done reading KPs as K
#pragma unroll
        for (int i = 0; i < 4; i++)
#pragma unroll
            for (int j = 0; j < 4; j++)
                KPs[(ty * 4 + i) * 65 + tx * 4 + j] = p[i][j];
        __syncthreads();

        // O += P @ V
#pragma unroll 4
        for (int c = 0; c < 64; c++) {
            float a0 = KPs[(ty * 4 + 0) * 65 + c];
            float a1 = KPs[(ty * 4 + 1) * 65 + c];
            float a2 = KPs[(ty * 4 + 2) * 65 + c];
            float a3 = KPs[(ty * 4 + 3) * 65 + c];
            float4 bv = *(const float4*)&Vs[c * 64 + tx * 4];
            acc[0][0] = fmaf(a0, bv.x, acc[0][0]); acc[0][1] = fmaf(a0, bv.y, acc[0][1]);
            acc[0][2] = fmaf(a0, bv.z, acc[0][2]); acc[0][3] = fmaf(a0, bv.w, acc[0][3]);
            acc[1][0] = fmaf(a1, bv.x, acc[1][0]); acc[1][1] = fmaf(a1, bv.y, acc[1][1]);
            acc[1][2] = fmaf(a1, bv.z, acc[1][2]); acc[1][3] = fmaf(a1, bv.w, acc[1][3]);
            acc[2][0] = fmaf(a2, bv.x, acc[2][0]); acc[2][1] = fmaf(a2, bv.y, acc[2][1]);
            acc[2][2] = fmaf(a2, bv.z, acc[2][2]); acc[2][3] = fmaf(a2, bv.w, acc[2][3]);
            acc[3][0] = fmaf(a3, bv.x, acc[3][0]); acc[3][1] = fmaf(a3, bv.y, acc[3][1]);
            acc[3][2] = fmaf(a3, bv.z, acc[3][2]); acc[3][3] = fmaf(a3, bv.w, acc[3][3]);
        }
    }

    const int b = bh >> 4, h = bh & 15;
#pragma unroll
    for (int i = 0; i < 4; i++) {
        float inv = 1.0f / l[i];
        int row = q0 + ty * 4 + i;
        float* o = O + ((size_t)(b * Sn + row)) * (Hn * Ln) + h * Ln + tx * 4;
#pragma unroll
        for (int j = 0; j < 4; j++) o[j] = acc[i][j] * inv;
    }
}

// ---------------- launch ----------------
extern "C" void kernel_launch(void* const* d_in, const int* in_sizes, int n_in,
                              void* d_out, int out_size)
{
    (void)in_sizes; (void)n_in; (void)out_size;
    const float* queries = (const float*)d_in[0];
    const float* keys    = (const float*)d_in[1];
    const float* values  = (const float*)d_in[2];
    const float* Wq      = (const float*)d_in[3];
    const float* bq      = (const float*)d_in[4];
    const float* Wlk     = (const float*)d_in[5];
    const float* blk     = (const float*)d_in[6];
    const float* Wlv     = (const float*)d_in[7];
    const float* blv     = (const float*)d_in[8];
    const float* Wkr     = (const float*)d_in[9];
    const float* Wvr     = (const float*)d_in[10];
    const float* Wout    = (const float*)d_in[11];
    const float* bout    = (const float*)d_in[12];
    float* out = (float*)d_out;

    float *wqk, *bqk, *wvo, *q, *lk, *lv, *olat;
    cudaGetSymbolAddress((void**)&wqk,  g_wqk);
    cudaGetSymbolAddress((void**)&bqk,  g_bqk);
    cudaGetSymbolAddress((void**)&wvo,  g_wvo);
    cudaGetSymbolAddress((void**)&q,    g_q);
    cudaGetSymbolAddress((void**)&lk,   g_lk);
    cudaGetSymbolAddress((void**)&lv,   g_lv);
    cudaGetSymbolAddress((void**)&olat, g_olat);

    const int flash_smem = (64 * 64 + 64 * 65 + 64 * 64) * 4;  // 49408 B
    cudaFuncSetAttribute(flash_kernel, cudaFuncAttributeMaxDynamicSharedMemorySize,
                         flash_smem);
    const int gemm_smem = (2 * BM * ASTR + 2 * BK * BSTR) * 4;  // 71680 B
    cudaFuncSetAttribute(tf32gemm, cudaFuncAttributeMaxDynamicSharedMemorySize,
                         gemm_smem);

    // absorbed weights
    wqk_kernel<<<dim3(16, 16), 128>>>(Wq, Wkr, wqk);
    bqk_kernel<<<4, 256>>>(bq, Wkr, bqk);
    wvo_kernel<<<dim3(16, 16), 128>>>(Wvr, Wout, wvo);

    // projections into latent space: [4096,2048]@[2048,1024] each
    tf32gemm<<<dim3(8, 32), 256, gemm_smem>>>(queries, wqk, bqk, q,  4096, 1024, 2048, 1);
    tf32gemm<<<dim3(8, 32), 256, gemm_smem>>>(keys,    Wlk, blk, lk, 4096, 1024, 2048, 1);
    tf32gemm<<<dim3(8, 32), 256, gemm_smem>>>(values,  Wlv, blv, lv, 4096, 1024, 2048, 1);

    // causal latent attention
    flash_kernel<<<dim3(Sn / 64, Bn * Hn), 256, flash_smem>>>(q, lk, lv, olat);

    // output projection: [4096,1024]@[1024,2048]
    tf32gemm<<<dim3(16, 32), 256, gemm_smem>>>(olat, wvo, bout, out, 4096, 2048, 1024, 0);
}

// round 3
// speedup vs baseline: 3.1365x; 1.5093x over previous
#include <cuda_runtime.h>
#include <math.h>
#include <stdint.h>

#define Bn  2
#define Sn  2048
#define Dn  2048
#define Hn  16
#define DKn 128
#define DVn 128
#define Ln  64

// ---------------- scratch (device globals) ----------------
__device__ float g_wqk[Dn * Hn * Ln];
__device__ float g_bqk[Hn * Ln];
__device__ float g_wvo[Hn * Ln * Dn];
__device__ float g_q  [Bn * Hn * Sn * Ln];   // [B,H,S,L] tf32, pre-scaled by log2e/sqrt(128)
__device__ float g_lk [Bn * Hn * Sn * Ln];   // [B,H,S,L] tf32
__device__ float g_lvT[Bn * Hn * Ln * Sn];   // [B,H,L,S] tf32 (transposed!)
__device__ float g_olat[Bn * Sn * Hn * Ln];  // [4096][1024]

__device__ __forceinline__ uint32_t f2tf32(float x) {
    uint32_t u;
    asm("cvt.rna.tf32.f32 %0, %1;" : "=r"(u) : "f"(x));
    return u;
}
__device__ __forceinline__ float tf32f(float x) { return __uint_as_float(f2tf32(x)); }

__device__ __forceinline__ void ldsm4(uint32_t* r, uint32_t a) {
    asm volatile("ldmatrix.sync.aligned.m8n8.x4.shared.b16 {%0,%1,%2,%3}, [%4];"
                 : "=r"(r[0]), "=r"(r[1]), "=r"(r[2]), "=r"(r[3]) : "r"(a));
}
__device__ __forceinline__ void ldsm2(uint32_t* r, uint32_t a) {
    asm volatile("ldmatrix.sync.aligned.m8n8.x2.shared.b16 {%0,%1}, [%2];"
                 : "=r"(r[0]), "=r"(r[1]) : "r"(a));
}
__device__ __forceinline__ void mma_tf32(float* c, const uint32_t* a, const uint32_t* b) {
    asm volatile(
        "mma.sync.aligned.m16n8k8.row.col.f32.tf32.tf32.f32 "
        "{%0,%1,%2,%3}, {%4,%5,%6,%7}, {%8,%9}, {%0,%1,%2,%3};\n"
        : "+f"(c[0]), "+f"(c[1]), "+f"(c[2]), "+f"(c[3])
        : "r"(a[0]), "r"(a[1]), "r"(a[2]), "r"(a[3]), "r"(b[0]), "r"(b[1]));
}
#define CPA16(dst, src) \
    asm volatile("cp.async.cg.shared.global [%0], [%1], 16;\n" :: "r"(dst), "l"(src))

// ---------------- weight precompute ----------------
__global__ void wqk_kernel(const float* __restrict__ Wq, const float* __restrict__ Wkr,
                           float* __restrict__ out)
{
    __shared__ float wkT[DKn][Ln];
    int t = threadIdx.x;
    for (int i = t; i < Ln * DKn; i += 128) {
        int l = i >> 7, dk = i & 127;
        wkT[dk][l] = Wkr[i];
    }
    __syncthreads();
    int h = blockIdx.y;
    int d = blockIdx.x * 128 + t;
    const float* wq = Wq + (size_t)d * Dn + h * DKn;
    float s[Ln];
#pragma unroll
    for (int l = 0; l < Ln; l++) s[l] = 0.f;
    for (int dk = 0; dk < DKn; dk++) {
        float a = wq[dk];
        const float4* w4 = (const float4*)&wkT[dk][0];
#pragma unroll
        for (int l4 = 0; l4 < Ln / 4; l4++) {
            float4 w = w4[l4];
            s[l4*4+0] = fmaf(a, w.x, s[l4*4+0]);
            s[l4*4+1] = fmaf(a, w.y, s[l4*4+1]);
            s[l4*4+2] = fmaf(a, w.z, s[l4*4+2]);
            s[l4*4+3] = fmaf(a, w.w, s[l4*4+3]);
        }
    }
    float* o = out + (size_t)d * (Hn * Ln) + h * Ln;
#pragma unroll
    for (int l4 = 0; l4 < Ln / 4; l4++)
        *(float4*)&o[l4*4] = make_float4(s[l4*4], s[l4*4+1], s[l4*4+2], s[l4*4+3]);
}

__global__ void bqk_kernel(const float* __restrict__ bq, const float* __restrict__ Wkr,
                           float* __restrict__ out)
{
    int hl = blockIdx.x * 256 + threadIdx.x;
    if (hl >= Hn * Ln) return;
    int h = hl >> 6, l = hl & 63;
    float s = 0.f;
#pragma unroll 8
    for (int dk = 0; dk < DKn; dk++)
        s = fmaf(bq[h * DKn + dk], Wkr[l * DKn + dk], s);
    out[hl] = s;
}

__global__ void wvo_kernel(const float* __restrict__ Wvr, const float* __restrict__ Wout,
                           float* __restrict__ out)
{
    __shared__ float wvT[DVn][Ln];
    int t = threadIdx.x;
    for (int i = t; i < Ln * DVn; i += 128) {
        int l = i >> 7, dv = i & 127;
        wvT[dv][l] = Wvr[i];
    }
    __syncthreads();
    int h = blockIdx.y;
    int d = blockIdx.x * 128 + t;
    float s[Ln];
#pragma unroll
    for (int l = 0; l < Ln; l++) s[l] = 0.f;
    for (int dv = 0; dv < DVn; dv++) {
        float a = Wout[(size_t)(h * DVn + dv) * Dn + d];
        const float4* w4 = (const float4*)&wvT[dv][0];
#pragma unroll
        for (int l4 = 0; l4 < Ln / 4; l4++) {
            float4 w = w4[l4];
            s[l4*4+0] = fmaf(a, w.x, s[l4*4+0]);
            s[l4*4+1] = fmaf(a, w.y, s[l4*4+1]);
            s[l4*4+2] = fmaf(a, w.z, s[l4*4+2]);
            s[l4*4+3] = fmaf(a, w.w, s[l4*4+3]);
        }
    }
    for (int l = 0; l < Ln; l++)
        out[(size_t)(h * Ln + l) * Dn + d] = s[l];
}

// ================= TF32 tensor-core GEMM =================
#define BM 128
#define BN 128
#define BK 32
#define ASTR 36
#define BSTR 136

struct GArgs {
    const float* A[3];
    const float* B[3];
    const float* bias[3];
    float*       C[3];
    int          mode[3];    // 0 plain, 1 latent remap+cvt(+presc), 2 latent transposed+cvt
    float        presc[3];
};

__global__ void __launch_bounds__(256, 2) tf32gemm(GArgs ga, int M, int N, int K)
{
    extern __shared__ float sm[];
    float (*As)[BM][ASTR] = (float (*)[BM][ASTR])sm;
    float (*Bs)[BK][BSTR] = (float (*)[BK][BSTR])(sm + 2 * BM * ASTR);

    const int z = blockIdx.z;
    const float* __restrict__ A    = ga.A[z];
    const float* __restrict__ B    = ga.B[z];
    const float* __restrict__ bias = ga.bias[z];
    float* __restrict__ C          = ga.C[z];
    const int   mode  = ga.mode[z];
    const float presc = ga.presc[z];

    const int tid  = threadIdx.x;
    const int lane = tid & 31, wid = tid >> 5;
    const int wm = wid & 3, wn = wid >> 2;
    const int g  = lane >> 2, tg = lane & 3;

    const int ar = tid >> 3;
    const int ac = (tid & 7) * 4;
    const int bk = tid >> 3;
    const int bc = (tid & 7) * 4;

    const float* Ab = A + (size_t)(blockIdx.y * BM) * K;
    const float* Bb = B + blockIdx.x * BN;

    float acc[2][8][4];
#pragma unroll
    for (int i = 0; i < 2; i++)
#pragma unroll
        for (int j = 0; j < 8; j++)
#pragma unroll
            for (int v = 0; v < 4; v++) acc[i][j][v] = 0.f;

    const int NKB = K / BK;
    {
#pragma unroll
        for (int p = 0; p < 4; p++) {
            unsigned d = (unsigned)__cvta_generic_to_shared(&As[0][ar + 32 * p][ac]);
            const float* s = Ab + (size_t)(ar + 32 * p) * K + ac;
            CPA16(d, s);
        }
#pragma unroll
        for (int j = 0; j < 4; j++) {
            unsigned d = (unsigned)__cvta_generic_to_shared(&Bs[0][bk][bc + 32 * j]);
            const float* s = Bb + (size_t)bk * N + bc + 32 * j;
            CPA16(d, s);
        }
        asm volatile("cp.async.commit_group;\n");
    }

    int buf = 0;
    for (int kb = 0; kb < NKB; kb++) {
        if (kb + 1 < NKB) {
            const int k0 = (kb + 1) * BK;
#pragma unroll
            for (int p = 0; p < 4; p++) {
                unsigned d = (unsigned)__cvta_generic_to_shared(&As[buf ^ 1][ar + 32 * p][ac]);
                const float* s = Ab + (size_t)(ar + 32 * p) * K + k0 + ac;
                CPA16(d, s);
            }
#pragma unroll
            for (int j = 0; j < 4; j++) {
                unsigned d = (unsigned)__cvta_generic_to_shared(&Bs[buf ^ 1][bk][bc + 32 * j]);
                const float* s = Bb + (size_t)(k0 + bk) * N + bc + 32 * j;
                CPA16(d, s);
            }
        }
        asm volatile("cp.async.commit_group;\n");
        asm volatile("cp.async.wait_group 1;\n");
        __syncthreads();

#pragma unroll
        for (int kk = 0; kk < 4; kk++) {
            const int k8 = kk * 8;
            uint32_t af[2][4];
#pragma unroll
            for (int mi = 0; mi < 2; mi++) {
                const int r = wm * 32 + mi * 16 + g;
                af[mi][0] = f2tf32(As[buf][r    ][k8 + tg]);
                af[mi][1] = f2tf32(As[buf][r + 8][k8 + tg]);
                af[mi][2] = f2tf32(As[buf][r    ][k8 + tg + 4]);
                af[mi][3] = f2tf32(As[buf][r + 8][k8 + tg + 4]);
            }
#pragma unroll
            for (int nt = 0; nt < 8; nt++) {
                const int n = wn * 64 + nt * 8 + g;
                uint32_t b[2];
                b[0] = f2tf32(Bs[buf][k8 + tg    ][n]);
                b[1] = f2tf32(Bs[buf][k8 + tg + 4][n]);
#pragma unroll
                for (int mi = 0; mi < 2; mi++)
                    mma_tf32(acc[mi][nt], af[mi], b);
            }
        }
        __syncthreads();
        buf ^= 1;
    }

    if (mode == 2) {
        // transposed latent epilogue: write [B,H,L,S] (tf32)
        float* Tr = sm;   // [128][132], 16896 floats <= 17920
#pragma unroll
        for (int mi = 0; mi < 2; mi++) {
#pragma unroll
            for (int nt = 0; nt < 8; nt++) {
                int r0 = wm * 32 + mi * 16 + g;
                int c  = wn * 64 + nt * 8 + 2 * tg;
                int cg = blockIdx.x * BN + c;
                float b0 = bias[cg], b1 = bias[cg + 1];
                Tr[r0 * 132 + c]       = acc[mi][nt][0] + b0;
                Tr[r0 * 132 + c + 1]   = acc[mi][nt][1] + b1;
                Tr[(r0+8) * 132 + c]   = acc[mi][nt][2] + b0;
                Tr[(r0+8) * 132 + c+1] = acc[mi][nt][3] + b1;
            }
        }
        __syncthreads();
#pragma unroll
        for (int cc = 0; cc < 16; cc++) {
            int c  = wid * 16 + cc;
            int cg = blockIdx.x * BN + c;
            int h = cg >> 6, l = cg & 63;
            int sg = blockIdx.y * BM + lane * 4;
            int b = sg >> 11, s = sg & 2047;
            float4 v;
            v.x = tf32f(Tr[(lane*4+0) * 132 + c]);
            v.y = tf32f(Tr[(lane*4+1) * 132 + c]);
            v.z = tf32f(Tr[(lane*4+2) * 132 + c]);
            v.w = tf32f(Tr[(lane*4+3) * 132 + c]);
            *(float4*)&C[((size_t)((b * Hn + h) * Ln + l)) * Sn + s] = v;
        }
        return;
    }

    const int rowb = blockIdx.y * BM + wm * 32 + g;
    const int colb = blockIdx.x * BN + wn * 64 + 2 * tg;
#pragma unroll
    for (int mi = 0; mi < 2; mi++) {
#pragma unroll
        for (int nt = 0; nt < 8; nt++) {
            const int col = colb + nt * 8;
            const float bv0 = bias[col], bv1 = bias[col + 1];
            const int r0 = rowb + mi * 16;
            const int r1 = r0 + 8;
            float2 v0 = make_float2(acc[mi][nt][0] + bv0, acc[mi][nt][1] + bv1);
            float2 v1 = make_float2(acc[mi][nt][2] + bv0, acc[mi][nt][3] + bv1);
            if (mode == 1) {
                v0.x = __uint_as_float(f2tf32(v0.x * presc));
                v0.y = __uint_as_float(f2tf32(v0.y * presc));
                v1.x = __uint_as_float(f2tf32(v1.x * presc));
                v1.y = __uint_as_float(f2tf32(v1.y * presc));
                const int h = col >> 6, l = col & 63;
                {
                    const int b = r0 >> 11, s = r0 & 2047;
                    *(float2*)&C[(((size_t)(b * Hn + h) * Sn + s) << 6) + l] = v0;
                }
                {
                    const int b = r1 >> 11, s = r1 & 2047;
                    *(float2*)&C[(((size_t)(b * Hn + h) * Sn + s) << 6) + l] = v1;
                }
            } else {
                *(float2*)&C[(size_t)r0 * N + col] = v0;
                *(float2*)&C[(size_t)r1 * N + col] = v1;
            }
        }
    }
}

// ================= tensor-core flash attention (latent d=64, causal) =================
// 128-row Q tile, 4 warps (32 rows each), ldmatrix fragments, inputs pre-tf32.
#define FSTR 68
__global__ void __launch_bounds__(128, 2) flash_tc(
    const float* __restrict__ Q, const float* __restrict__ Kl,
    const float* __restrict__ VT, float* __restrict__ O)
{
    extern __shared__ float sm[];
    // Qs [128][68], Ps [128][68], Ks [64][68], Vs [64][68]
    const int QS = 0;
    const int PS = 128 * FSTR;
    const int KS = 2 * 128 * FSTR;
    const int VS = KS + 64 * FSTR;

    const int tid  = threadIdx.x;
    const int lane = tid & 31, wid = tid >> 5;
    const int g = lane >> 2, tg = lane & 3;

    const int qt = gridDim.x - 1 - blockIdx.x;   // big tiles first
    const int bh = blockIdx.y;
    const int q0 = qt * 128;

    const float* Qg = Q  + ((size_t)bh * Sn + q0) * Ln;
    const float* Kg = Kl + (size_t)bh * Sn * Ln;
    const float* Vg = VT + (size_t)bh * Ln * Sn;   // [dv][s]

    uint32_t smb = (uint32_t)__cvta_generic_to_shared(sm);

    // ldmatrix per-thread addresses (bytes)
    const int r8 = lane & 7, rh = (lane >> 3) & 1, ch = (lane >> 4) & 1;
    const uint32_t qAddr = smb + QS * 4 + ((wid * 32 + r8 + rh * 8) * FSTR + ch * 4) * 4;
    const uint32_t pAddr = smb + PS * 4 + ((wid * 32 + r8 + rh * 8) * FSTR + ch * 4) * 4;
    const int l4 = lane & 15;
    const uint32_t kAddr = smb + KS * 4 + ((l4 & 7) * FSTR + ((l4 >> 3) * 4)) * 4;
    const uint32_t vAddr = smb + VS * 4 + ((l4 & 7) * FSTR + ((l4 >> 3) * 4)) * 4;

    // initial loads: Q (once) + K/V tile 0
#pragma unroll
    for (int i = 0; i < 16; i++) {
        int idx = tid + i * 128;
        int row = idx >> 4, c = (idx & 15) * 4;
        CPA16(smb + (QS + row * FSTR + c) * 4, Qg + row * 64 + c);
    }
#pragma unroll
    for (int i = 0; i < 8; i++) {
        int idx = tid + i * 128;
        int row = idx >> 4, c = (idx & 15) * 4;
        CPA16(smb + (KS + row * FSTR + c) * 4, Kg + (size_t)row * 64 + c);
        CPA16(smb + (VS + row * FSTR + c) * 4, Vg + (size_t)row * Sn + c);
    }
    asm volatile("cp.async.commit_group;\n");

    float oacc[2][8][4];
    float mrow[2][2], lrow[2][2];
#pragma unroll
    for (int mi = 0; mi < 2; mi++) {
        mrow[mi][0] = mrow[mi][1] = -1e30f;
        lrow[mi][0] = lrow[mi][1] = 0.f;
#pragma unroll
        for (int nt = 0; nt < 8; nt++)
#pragma unroll
            for (int v = 0; v < 4; v++) oacc[mi][nt][v] = 0.f;
    }

    const int ktmax = 2 * qt + 2;
    for (int kt = 0; kt < ktmax; kt++) {
        asm volatile("cp.async.wait_group 0;\n");
        __syncthreads();

        // ---- S = Q @ K^T ----
        float sacc[2][8][4];
#pragma unroll
        for (int mi = 0; mi < 2; mi++)
#pragma unroll
            for (int nt = 0; nt < 8; nt++)
#pragma unroll
                for (int v = 0; v < 4; v++) sacc[mi][nt][v] = 0.f;

#pragma unroll
        for (int kk = 0; kk < 8; kk++) {
            uint32_t qa[2][4];
            ldsm4(qa[0], qAddr + kk * 32);
            ldsm4(qa[1], qAddr + 16 * FSTR * 4 + kk * 32);
#pragma unroll
            for (int nt = 0; nt < 8; nt++) {
                uint32_t kb[2];
                ldsm2(kb, kAddr + nt * 8 * FSTR * 4 + kk * 32);
                mma_tf32(sacc[0][nt], qa[0], kb);
                mma_tf32(sacc[1][nt], qa[1], kb);
            }
        }

        // ---- causal mask (last two tiles only) ----
        if (kt >= 2 * qt) {
            const int colb = kt * 64 + 2 * tg;
#pragma unroll
            for (int mi = 0; mi < 2; mi++) {
                const int rb = q0 + wid * 32 + mi * 16 + g;
#pragma unroll
                for (int nt = 0; nt < 8; nt++) {
                    const int c = colb + 8 * nt;
                    if (c     > rb)     sacc[mi][nt][0] = -1e30f;
                    if (c + 1 > rb)     sacc[mi][nt][1] = -1e30f;
                    if (c     > rb + 8) sacc[mi][nt][2] = -1e30f;
                    if (c + 1 > rb + 8) sacc[mi][nt][3] = -1e30f;
                }
            }
        }

        // ---- online softmax (scores already in log2 units) ----
#pragma unroll
        for (int mi = 0; mi < 2; mi++) {
#pragma unroll
            for (int hh = 0; hh < 2; hh++) {
                float rm = -1e30f;
#pragma unroll
                for (int nt = 0; nt < 8; nt++)
                    rm = fmaxf(rm, fmaxf(sacc[mi][nt][2*hh], sacc[mi][nt][2*hh+1]));
                rm = fmaxf(rm, __shfl_xor_sync(0xffffffffu, rm, 1));
                rm = fmaxf(rm, __shfl_xor_sync(0xffffffffu, rm, 2));
                float mo = mrow[mi][hh];
                float mn = fmaxf(mo, rm);
                float fac = exp2f(mo - mn);
                float rs = 0.f;
                const int prow = wid * 32 + mi * 16 + hh * 8 + g;
#pragma unroll
                for (int nt = 0; nt < 8; nt++) {
                    float p0 = exp2f(sacc[mi][nt][2*hh]   - mn);
                    float p1 = exp2f(sacc[mi][nt][2*hh+1] - mn);
                    rs += p0 + p1;
                    *(float2*)&sm[PS + prow * FSTR + nt * 8 + 2 * tg] = make_float2(p0, p1);
                    oacc[mi][nt][2*hh]   *= fac;
                    oacc[mi][nt][2*hh+1] *= fac;
                }
                rs += __shfl_xor_sync(0xffffffffu, rs, 1);
                rs += __shfl_xor_sync(0xffffffffu, rs, 2);
                lrow[mi][hh] = lrow[mi][hh] * fac + rs;
                mrow[mi][hh] = mn;
            }
        }
        __syncwarp();

        // ---- O += P @ V ----
#pragma unroll
        for (int kk = 0; kk < 8; kk++) {
            uint32_t pa[2][4];
            ldsm4(pa[0], pAddr + kk * 32);
            ldsm4(pa[1], pAddr + 16 * FSTR * 4 + kk * 32);
#pragma unroll
            for (int nt = 0; nt < 8; nt++) {
                uint32_t vb[2];
                ldsm2(vb, vAddr + nt * 8 * FSTR * 4 + kk * 32);
                mma_tf32(oacc[0][nt], pa[0], vb);
                mma_tf32(oacc[1][nt], pa[1], vb);
            }
        }

        __syncthreads();   // all warps done with Ks/Vs
        if (kt + 1 < ktmax) {
            const int kbase = (kt + 1) * 64;
#pragma unroll
            for (int i = 0; i < 8; i++) {
                int idx = tid + i * 128;
                int row = idx >> 4, c = (idx & 15) * 4;
                CPA16(smb + (KS + row * FSTR + c) * 4,
                      Kg + (size_t)(kbase + row) * 64 + c);
                CPA16(smb + (VS + row * FSTR + c) * 4,
                      Vg + (size_t)row * Sn + kbase + c);
            }
        }
        asm volatile("cp.async.commit_group;\n");
    }

    // ---- write O / l ----
    const int b = bh >> 4, h = bh & 15;
#pragma unroll
    for (int mi = 0; mi < 2; mi++) {
#pragma unroll
        for (int hh = 0; hh < 2; hh++) {
            float inv = 1.0f / lrow[mi][hh];
            int row = q0 + wid * 32 + mi * 16 + hh * 8 + g;
            float* o = O + ((size_t)(b * Sn + row)) * (Hn * Ln) + h * Ln + 2 * tg;
#pragma unroll
            for (int nt = 0; nt < 8; nt++) {
                float2 v = make_float2(oacc[mi][nt][2*hh] * inv, oacc[mi][nt][2*hh+1] * inv);
                *(float2*)&o[nt * 8] = v;
            }
        }
    }
}

// ---------------- launch ----------------
extern "C" void kernel_launch(void* const* d_in, const int* in_sizes, int n_in,
                              void* d_out, int out_size)
{
    (void)in_sizes; (void)n_in; (void)out_size;
    const float* queries = (const float*)d_in[0];
    const float* keys    = (const float*)d_in[1];
    const float* values  = (const float*)d_in[2];
    const float* Wq      = (const float*)d_in[3];
    const float* bq      = (const float*)d_in[4];
    const float* Wlk     = (const float*)d_in[5];
    const float* blk     = (const float*)d_in[6];
    const float* Wlv     = (const float*)d_in[7];
    const float* blv     = (const float*)d_in[8];
    const float* Wkr     = (const float*)d_in[9];
    const float* Wvr     = (const float*)d_in[10];
    const float* Wout    = (const float*)d_in[11];
    const float* bout    = (const float*)d_in[12];
    float* out = (float*)d_out;

    float *wqk, *bqk, *wvo, *q, *lk, *lvT, *olat;
    cudaGetSymbolAddress((void**)&wqk,  g_wqk);
    cudaGetSymbolAddress((void**)&bqk,  g_bqk);
    cudaGetSymbolAddress((void**)&wvo,  g_wvo);
    cudaGetSymbolAddress((void**)&q,    g_q);
    cudaGetSymbolAddress((void**)&lk,   g_lk);
    cudaGetSymbolAddress((void**)&lvT,  g_lvT);
    cudaGetSymbolAddress((void**)&olat, g_olat);

    const int gemm_smem  = (2 * BM * ASTR + 2 * BK * BSTR) * 4;   // 71680 B
    const int flash_smem = (2 * 128 * FSTR + 2 * 64 * FSTR) * 4;  // 104448 B
    cudaFuncSetAttribute(tf32gemm, cudaFuncAttributeMaxDynamicSharedMemorySize, gemm_smem);
    cudaFuncSetAttribute(flash_tc, cudaFuncAttributeMaxDynamicSharedMemorySize, flash_smem);

    // absorbed weights
    wqk_kernel<<<dim3(16, 16), 128>>>(Wq, Wkr, wqk);
    bqk_kernel<<<4, 256>>>(bq, Wkr, bqk);
    wvo_kernel<<<dim3(16, 16), 128>>>(Wvr, Wout, wvo);

    // fused projections: q (scaled tf32), lk (tf32), lvT (tf32, transposed)
    const float presc_q = 1.4426950408889634f / 11.313708498984761f;  // log2e/sqrt(128)
    GArgs pa;
    pa.A[0] = queries; pa.B[0] = wqk; pa.bias[0] = bqk;  pa.C[0] = q;    pa.mode[0] = 1; pa.presc[0] = presc_q;
    pa.A[1] = keys;    pa.B[1] = Wlk; pa.bias[1] = blk;  pa.C[1] = lk;   pa.mode[1] = 1; pa.presc[1] = 1.0f;
    pa.A[2] = values;  pa.B[2] = Wlv; pa.bias[2] = blv;  pa.C[2] = lvT;  pa.mode[2] = 2; pa.presc[2] = 1.0f;
    tf32gemm<<<dim3(8, 32, 3), 256, gemm_smem>>>(pa, 4096, 1024, 2048);

    // tensor-core causal latent attention
    flash_tc<<<dim3(Sn / 128, Bn * Hn), 128, flash_smem>>>(q, lk, lvT, olat);

    // output projection
    GArgs po;
    po.A[0] = olat; po.B[0] = wvo; po.bias[0] = bout; po.C[0] = out; po.mode[0] = 0; po.presc[0] = 1.0f;
    tf32gemm<<<dim3(16, 32, 1), 256, gemm_smem>>>(po, 4096, 2048, 1024);
}